// round 12
// baseline (speedup 1.0000x reference)
#include <cuda_runtime.h>
#include <cuda_fp16.h>
#include <math.h>
#include <stdint.h>

// ---------------- problem constants ----------------
#define N_NODES 50000
#define N_EDGES 200000
#define E_TOT   (N_EDGES + N_NODES)   // 250000
#define F0      74
#define K1PAD   96
#define H1      4
#define D1      256
#define HD1     (H1 * D1)             // 1024
#define D2      256
#define N_GRAPHS 256
#define OUT_DIM 12
#define NEG_SLOPE 0.2f

// ---------------- scratch ----------------
__device__ __half g_h2 [(size_t)N_NODES * D2];
__device__ float  g_out2[(size_t)N_NODES * D2];
__device__ float g_als1[N_NODES * H1];
__device__ float g_ald1[N_NODES * H1];
__device__ float g_als2[N_NODES];
__device__ float g_ald2[N_NODES];
__device__ int   g_deg[N_NODES];      // zeroed by previous call's k_pool_fc (or static init)
__device__ int   g_rowptr[N_NODES + 1];
__device__ int   g_cursor[N_NODES];
__device__ int   g_elist[E_TOT];
__device__ int   g_src[E_TOT];
__device__ int   g_dst[E_TOT];

// attention projection vectors
__device__ float g_was1[K1PAD * H1];
__device__ float g_wad1[K1PAD * H1];
__device__ float g_was2[HD1];
__device__ float g_wad2[HD1];

// GEMM operands (fp16, K-major, 16B-aligned)
__device__ uint4 g_xagg[(size_t)N_NODES * H1 * K1PAD / 8];
__device__ uint4 g_w1  [(size_t)HD1 * K1PAD / 8];
__device__ uint4 g_o1  [(size_t)N_NODES * HD1 / 8];
__device__ uint4 g_w2  [(size_t)D2 * HD1 / 8];

// ---------------- PTX helpers ----------------
__device__ __forceinline__ uint32_t smem_u32(const void* p) {
    uint32_t a;
    asm("{ .reg .u64 t; cvta.to.shared.u64 t, %1; cvt.u32.u64 %0, t; }" : "=r"(a) : "l"(p));
    return a;
}
#define CP_ASYNC16(dst, src) \
    asm volatile("cp.async.cg.shared.global [%0], [%1], 16;" :: "r"(dst), "l"(src))
#define CP_COMMIT() asm volatile("cp.async.commit_group;" ::: "memory")
#define CP_WAIT1()  asm volatile("cp.async.wait_group 1;" ::: "memory")
#define CP_WAIT3()  asm volatile("cp.async.wait_group 3;" ::: "memory")

#define LDSM_X4(r, addr) \
    asm volatile("ldmatrix.sync.aligned.m8n8.x4.shared.b16 {%0,%1,%2,%3}, [%4];" \
        : "=r"((r)[0]), "=r"((r)[1]), "=r"((r)[2]), "=r"((r)[3]) : "r"(addr))

#define MMA_FP16(d, a, b) \
    asm volatile("mma.sync.aligned.m16n8k16.row.col.f32.f16.f16.f32 " \
        "{%0,%1,%2,%3}, {%4,%5,%6,%7}, {%8,%9}, {%0,%1,%2,%3};" \
        : "+f"((d)[0]), "+f"((d)[1]), "+f"((d)[2]), "+f"((d)[3]) \
        : "r"((a)[0]), "r"((a)[1]), "r"((a)[2]), "r"((a)[3]), "r"((b)[0]), "r"((b)[1]))

// ---------------- misc ----------------
__device__ __forceinline__ int detect_i64(const int* p) {
    return (p[1] | p[3] | p[5] | p[7]) == 0;
}
__device__ __forceinline__ float leaky(float v) { return v >= 0.f ? v : NEG_SLOPE * v; }

// ---------------- launch 0: setup ----------------
#define PW1_B 384
#define PW2_B 1024
#define AV1_B 37
#define AV2_B 128
#define PE_B  ((E_TOT + 255) / 256)   // 977
#define SETUP_GRID (PW1_B + PW2_B + AV1_B + AV2_B + PE_B)

__global__ __launch_bounds__(256) void k_setup(
    const float* __restrict__ W1, const float* __restrict__ W2,
    const float* __restrict__ as1, const float* __restrict__ ad1,
    const float* __restrict__ as2, const float* __restrict__ ad2,
    const int* __restrict__ ei32)
{
    int b = blockIdx.x, t = threadIdx.x, lane = t & 31;
    if (b < PW1_B) {
        int i = b * 256 + t;
        if (i < HD1 * K1PAD) {
            int n = i / K1PAD, k = i - n * K1PAD;
            float v = (k < F0) ? W1[(size_t)k * HD1 + n] : 0.f;
            ((__half*)g_w1)[i] = __float2half_rn(v);
        }
    } else if (b < PW1_B + PW2_B) {
        int i = (b - PW1_B) * 256 + t;
        if (i < D2 * HD1) {
            int n = i >> 10, k = i & 1023;
            ((__half*)g_w2)[i] = __float2half_rn(W2[(size_t)k * D2 + n]);
        }
    } else if (b < PW1_B + PW2_B + AV1_B) {
        int w = ((b - PW1_B - PW2_B) * 256 + t) >> 5;
        if (w < F0 * H1) {
            int k = w >> 2, h = w & 3;
            float s = 0.f, d = 0.f;
            for (int j = lane; j < D1; j += 32) {
                float wv = W1[(size_t)k * HD1 + h * D1 + j];
                s = fmaf(wv, as1[h * D1 + j], s);
                d = fmaf(wv, ad1[h * D1 + j], d);
            }
#pragma unroll
            for (int o = 16; o; o >>= 1) {
                s += __shfl_xor_sync(0xffffffffu, s, o);
                d += __shfl_xor_sync(0xffffffffu, d, o);
            }
            if (lane == 0) { g_was1[k * 4 + h] = s; g_wad1[k * 4 + h] = d; }
        }
    } else if (b < PW1_B + PW2_B + AV1_B + AV2_B) {
        int w = ((b - PW1_B - PW2_B - AV1_B) * 256 + t) >> 5;
        if (w < HD1) {
            float s = 0.f, d = 0.f;
            for (int j = lane; j < D2; j += 32) {
                float wv = W2[(size_t)w * D2 + j];
                s = fmaf(wv, as2[j], s);
                d = fmaf(wv, ad2[j], d);
            }
#pragma unroll
            for (int o = 16; o; o >>= 1) {
                s += __shfl_xor_sync(0xffffffffu, s, o);
                d += __shfl_xor_sync(0xffffffffu, d, o);
            }
            if (lane == 0) { g_was2[w] = s; g_wad2[w] = d; }
        }
    } else {
        int e = (b - PW1_B - PW2_B - AV1_B - AV2_B) * 256 + t;
        if (e >= E_TOT) return;
        int is64 = detect_i64(ei32);
        int s, d;
        if (e < N_EDGES) {
            s = is64 ? ei32[2 * (size_t)e]             : ei32[e];
            d = is64 ? ei32[2 * ((size_t)N_EDGES + e)] : ei32[N_EDGES + e];
        } else {
            s = d = e - N_EDGES;
        }
        g_src[e] = s;
        g_dst[e] = d;
        atomicAdd(&g_deg[d], 1);
    }
}

// ---------------- launch 1: scan (block 0) + layer-1 logits ----------------
#define SL_GRID (1 + (N_NODES + 31) / 32)

__global__ __launch_bounds__(1024) void k_scanlogit(const float* __restrict__ x) {
    if (blockIdx.x == 0) {
        __shared__ int sums[1024];
        int t = threadIdx.x;
        const int CH = (N_NODES + 1023) / 1024;
        int b = t * CH, e = min(b + CH, N_NODES);
        int s = 0;
        for (int i = b; i < e; i++) s += g_deg[i];
        sums[t] = s;
        __syncthreads();
        for (int off = 1; off < 1024; off <<= 1) {
            int v = (t >= off) ? sums[t - off] : 0;
            __syncthreads();
            sums[t] += v;
            __syncthreads();
        }
        int run = sums[t] - s;
        for (int i = b; i < e; i++) {
            g_rowptr[i] = run;
            g_cursor[i] = run;
            run += g_deg[i];
        }
        if (t == 1023) g_rowptr[N_NODES] = sums[1023];
        return;
    }
    int n = (blockIdx.x - 1) * 32 + (threadIdx.x >> 5);
    int lane = threadIdx.x & 31;
    if (n >= N_NODES) return;
    float4 s = make_float4(0, 0, 0, 0), d = make_float4(0, 0, 0, 0);
    for (int k = lane; k < F0; k += 32) {
        float xv = __ldg(&x[(size_t)n * F0 + k]);
        float4 a = *(const float4*)(g_was1 + k * 4);
        float4 bb = *(const float4*)(g_wad1 + k * 4);
        s.x = fmaf(xv, a.x, s.x);  s.y = fmaf(xv, a.y, s.y);
        s.z = fmaf(xv, a.z, s.z);  s.w = fmaf(xv, a.w, s.w);
        d.x = fmaf(xv, bb.x, d.x); d.y = fmaf(xv, bb.y, d.y);
        d.z = fmaf(xv, bb.z, d.z); d.w = fmaf(xv, bb.w, d.w);
    }
#pragma unroll
    for (int o = 16; o; o >>= 1) {
        s.x += __shfl_xor_sync(0xffffffffu, s.x, o);
        s.y += __shfl_xor_sync(0xffffffffu, s.y, o);
        s.z += __shfl_xor_sync(0xffffffffu, s.z, o);
        s.w += __shfl_xor_sync(0xffffffffu, s.w, o);
        d.x += __shfl_xor_sync(0xffffffffu, d.x, o);
        d.y += __shfl_xor_sync(0xffffffffu, d.y, o);
        d.z += __shfl_xor_sync(0xffffffffu, d.z, o);
        d.w += __shfl_xor_sync(0xffffffffu, d.w, o);
    }
    if (lane == 0) {
        *(float4*)(g_als1 + n * 4) = s;
        *(float4*)(g_ald1 + n * 4) = d;
    }
}

// ---------------- launch 2: scatter ----------------
__global__ void k_scatter() {
    int e = blockIdx.x * blockDim.x + threadIdx.x;
    if (e >= E_TOT) return;
    int p = atomicAdd(&g_cursor[g_dst[e]], 1);
    g_elist[p] = e;
}

// ---------------- launch 3 (PROFILED): layer-1 aggregate, pipelined gather --
__global__ __launch_bounds__(256) void k_aggx(const float* __restrict__ x) {
    int n = (blockIdx.x * blockDim.x + threadIdx.x) >> 5;
    int lane = threadIdx.x & 31;
    if (n >= N_NODES) return;
    if (lane == 0) { g_als2[n] = 0.f; g_ald2[n] = 0.f; }
    int start = g_rowptr[n], deg = g_rowptr[n + 1] - start;
    const float4 adn = *(const float4*)(g_ald1 + n * 4);

    float a[3][4];
#pragma unroll
    for (int g = 0; g < 3; g++)
#pragma unroll
        for (int h = 0; h < 4; h++) a[g][h] = 0.f;
    float4 den = make_float4(0, 0, 0, 0);

    for (int c0 = 0; c0 < deg; c0 += 32) {
        int j = c0 + lane;
        int srcj = 0;
        float4 e = make_float4(0, 0, 0, 0);
        if (j < deg) {
            int ed = g_elist[start + j];
            srcj = g_src[ed];
            float4 as = *(const float4*)(g_als1 + srcj * 4);
            e.x = expf(leaky(as.x + adn.x));
            e.y = expf(leaky(as.y + adn.y));
            e.z = expf(leaky(as.z + adn.z));
            e.w = expf(leaky(as.w + adn.w));
            den.x += e.x; den.y += e.y; den.z += e.z; den.w += e.w;
        }
        int cnt = min(32, deg - c0);

        // software-pipelined gather: prefetch edge jj+1's x row during jj's FMAs
        int s0v = __shfl_sync(0xffffffffu, srcj, 0);
        const float* xr0 = x + (size_t)s0v * F0;
        float px0 = __ldg(xr0 + lane);
        float px1 = __ldg(xr0 + lane + 32);
        float px2 = (lane + 64 < F0) ? __ldg(xr0 + lane + 64) : 0.f;

        for (int jj = 0; jj < cnt; jj++) {
            float x0 = px0, x1 = px1, x2 = px2;
            if (jj + 1 < cnt) {
                int sn = __shfl_sync(0xffffffffu, srcj, jj + 1);
                const float* xn = x + (size_t)sn * F0;
                px0 = __ldg(xn + lane);
                px1 = __ldg(xn + lane + 32);
                px2 = (lane + 64 < F0) ? __ldg(xn + lane + 64) : 0.f;
            }
            float e0 = __shfl_sync(0xffffffffu, e.x, jj);
            float e1 = __shfl_sync(0xffffffffu, e.y, jj);
            float e2 = __shfl_sync(0xffffffffu, e.z, jj);
            float e3 = __shfl_sync(0xffffffffu, e.w, jj);
            a[0][0] = fmaf(x0, e0, a[0][0]); a[0][1] = fmaf(x0, e1, a[0][1]);
            a[0][2] = fmaf(x0, e2, a[0][2]); a[0][3] = fmaf(x0, e3, a[0][3]);
            a[1][0] = fmaf(x1, e0, a[1][0]); a[1][1] = fmaf(x1, e1, a[1][1]);
            a[1][2] = fmaf(x1, e2, a[1][2]); a[1][3] = fmaf(x1, e3, a[1][3]);
            a[2][0] = fmaf(x2, e0, a[2][0]); a[2][1] = fmaf(x2, e1, a[2][1]);
            a[2][2] = fmaf(x2, e2, a[2][2]); a[2][3] = fmaf(x2, e3, a[2][3]);
        }
    }
#pragma unroll
    for (int o = 16; o; o >>= 1) {
        den.x += __shfl_xor_sync(0xffffffffu, den.x, o);
        den.y += __shfl_xor_sync(0xffffffffu, den.y, o);
        den.z += __shfl_xor_sync(0xffffffffu, den.z, o);
        den.w += __shfl_xor_sync(0xffffffffu, den.w, o);
    }
    float inv[4];
    inv[0] = 1.f / (den.x + 1e-16f);
    inv[1] = 1.f / (den.y + 1e-16f);
    inv[2] = 1.f / (den.z + 1e-16f);
    inv[3] = 1.f / (den.w + 1e-16f);

    __half* xa = (__half*)g_xagg + (size_t)n * (H1 * K1PAD);
#pragma unroll
    for (int g = 0; g < 3; g++) {
        int col = lane + 32 * g;
#pragma unroll
        for (int h = 0; h < 4; h++)
            xa[h * K1PAD + col] = __float2half_rn(a[g][h] * inv[h]);
    }
}

// ---------------- layer-2 aggregate, pipelined gather ----------------
__global__ __launch_bounds__(256) void k_agg2(const float* __restrict__ b2) {
    int n = (blockIdx.x * blockDim.x + threadIdx.x) >> 5;
    int lane = threadIdx.x & 31;
    if (n >= N_NODES) return;
    int start = g_rowptr[n], deg = g_rowptr[n + 1] - start;
    const float adn = g_ald2[n];

    float2 acc[4];
#pragma unroll
    for (int q = 0; q < 4; q++) acc[q] = make_float2(0.f, 0.f);
    float den = 0.f;

    for (int c0 = 0; c0 < deg; c0 += 32) {
        int j = c0 + lane;
        int srcj = 0;
        float e = 0.f;
        if (j < deg) {
            int ed = g_elist[start + j];
            srcj = g_src[ed];
            e = expf(leaky(g_als2[srcj] + adn));
            den += e;
        }
        int cnt = min(32, deg - c0);

        int s0v = __shfl_sync(0xffffffffu, srcj, 0);
        const __half2* hr0 = (const __half2*)(g_h2 + (size_t)s0v * D2);
        __half2 pv[4];
#pragma unroll
        for (int q = 0; q < 4; q++) pv[q] = __ldg(hr0 + lane + 32 * q);

        for (int jj = 0; jj < cnt; jj++) {
            __half2 cv[4];
#pragma unroll
            for (int q = 0; q < 4; q++) cv[q] = pv[q];
            if (jj + 1 < cnt) {
                int sn = __shfl_sync(0xffffffffu, srcj, jj + 1);
                const __half2* hn = (const __half2*)(g_h2 + (size_t)sn * D2);
#pragma unroll
                for (int q = 0; q < 4; q++) pv[q] = __ldg(hn + lane + 32 * q);
            }
            float ev = __shfl_sync(0xffffffffu, e, jj);
#pragma unroll
            for (int q = 0; q < 4; q++) {
                float2 v = __half22float2(cv[q]);
                acc[q].x = fmaf(v.x, ev, acc[q].x);
                acc[q].y = fmaf(v.y, ev, acc[q].y);
            }
        }
    }
#pragma unroll
    for (int o = 16; o; o >>= 1) den += __shfl_xor_sync(0xffffffffu, den, o);
    float inv = 1.f / (den + 1e-16f);

#pragma unroll
    for (int q = 0; q < 4; q++) {
        int c = 2 * (lane + 32 * q);
        float2 o;
        o.x = fmaxf(fmaf(acc[q].x, inv, 0.f) + __ldg(b2 + c),     0.f);
        o.y = fmaxf(fmaf(acc[q].y, inv, 0.f) + __ldg(b2 + c + 1), 0.f);
        *(float2*)&g_out2[(size_t)n * D2 + c] = o;
    }
}

// ---------------- GEMM tiles ----------------
#define SMSTRIDE 80
#define TILE_B   (128 * SMSTRIDE)

// ================= GEMM1: persistent B-stationary =================
#define MT1 8
#define GB1_Y 49
#define GM1_SMEM (3 * TILE_B + 2 * 3 * TILE_B)    // 92160 B

__global__ __launch_bounds__(256, 2) void k_mma1(
    const uint4* __restrict__ A1, const uint4* __restrict__ B1,
    __half* __restrict__ C, int M,
    const float* __restrict__ bias,
    const float* __restrict__ avs, const float* __restrict__ avd,
    float* __restrict__ als, float* __restrict__ ald)
{
    extern __shared__ char smem[];
    const uint32_t sbase = smem_u32(smem);
    const uint32_t abase = sbase + 3 * TILE_B;
    const int tid = threadIdx.x, lane = tid & 31, wid = tid >> 5;
    const int wm = wid & 1, wn = wid >> 1;
    const int n0 = blockIdx.x * 128;
    const int head = n0 >> 8;
    const int tile0 = blockIdx.y * MT1;
    const int KW = 12;
    const int AST = H1 * KW;

    float bv[4][2], av_s[4][2], av_d[4][2];
#pragma unroll
    for (int nt = 0; nt < 4; nt++) {
        int c = n0 + wn * 32 + nt * 8 + (lane & 3) * 2;
        bv[nt][0]   = bias[c]; bv[nt][1]   = bias[c + 1];
        av_s[nt][0] = avs[c];  av_s[nt][1] = avs[c + 1];
        av_d[nt][0] = avd[c];  av_d[nt][1] = avd[c + 1];
    }

    auto load_A = [&](int tile, int s) {
        uint32_t sb = abase + s * (3 * TILE_B);
        int m0 = tile * 128;
#pragma unroll
        for (int i = 0; i < 6; i++) {
            int idx = tid + i * 256;
            int chunk = idx / 512, rem = idx & 511;
            int row = rem >> 2, ch = rem & 3;
            int ar = min(m0 + row, M - 1);
            CP_ASYNC16(sb + chunk * TILE_B + row * SMSTRIDE + ch * 16,
                       A1 + (size_t)ar * AST + head * KW + chunk * 4 + ch);
        }
    };

#pragma unroll
    for (int i = 0; i < 6; i++) {
        int idx = tid + i * 256;
        int chunk = idx / 512, rem = idx & 511;
        int row = rem >> 2, ch = rem & 3;
        CP_ASYNC16(sbase + chunk * TILE_B + row * SMSTRIDE + ch * 16,
                   B1 + (size_t)(n0 + row) * KW + chunk * 4 + ch);
    }
    load_A(tile0, 0);
    CP_COMMIT();

    for (int g = 0; g < MT1; g++) {
        if (g + 1 < MT1) load_A(tile0 + g + 1, (g + 1) & 1);
        CP_COMMIT();
        CP_WAIT1();
        __syncthreads();

        float acc[4][4][4];
#pragma unroll
        for (int a = 0; a < 4; a++)
#pragma unroll
            for (int b = 0; b < 4; b++)
#pragma unroll
                for (int c = 0; c < 4; c++) acc[a][b][c] = 0.f;

        uint32_t ab = abase + (g & 1) * (3 * TILE_B);
#pragma unroll
        for (int ki = 0; ki < 3; ki++) {
            uint32_t b1b = sbase + ki * TILE_B;
            uint32_t a1b = ab + ki * TILE_B;
#pragma unroll
            for (int k16 = 0; k16 < 2; k16++) {
                uint32_t bf1[8];
#pragma unroll
                for (int gg = 0; gg < 2; gg++) {
                    int nrow = wn * 32 + gg * 16 + (lane & 7) + ((lane >> 4) << 3);
                    int kb   = k16 * 32 + (((lane >> 3) & 1) << 4);
                    LDSM_X4(&bf1[gg * 4], b1b + nrow * SMSTRIDE + kb);
                }
#pragma unroll
                for (int mt = 0; mt < 4; mt++) {
                    int arow = wm * 64 + mt * 16 + (lane & 7) + (((lane >> 3) & 1) << 3);
                    int kb   = k16 * 32 + ((lane >> 4) << 4);
                    uint32_t af[4];
                    LDSM_X4(af, a1b + arow * SMSTRIDE + kb);
#pragma unroll
                    for (int nt = 0; nt < 4; nt++) MMA_FP16(acc[mt][nt], af, &bf1[nt * 2]);
                }
            }
        }

        int m0 = (tile0 + g) * 128;
#pragma unroll
        for (int mt = 0; mt < 4; mt++) {
            int r = m0 + wm * 64 + mt * 16 + (lane >> 2);
            float s0 = 0.f, s1 = 0.f, d0 = 0.f, d1 = 0.f;
#pragma unroll
            for (int nt = 0; nt < 4; nt++) {
                int c = n0 + wn * 32 + nt * 8 + (lane & 3) * 2;
                float v0 = fmaxf(acc[mt][nt][0] + bv[nt][0], 0.f);
                float v1 = fmaxf(acc[mt][nt][1] + bv[nt][1], 0.f);
                float v2 = fmaxf(acc[mt][nt][2] + bv[nt][0], 0.f);
                float v3 = fmaxf(acc[mt][nt][3] + bv[nt][1], 0.f);
                if (r < M)
                    *(__half2*)&C[(size_t)r * HD1 + c] = __floats2half2_rn(v0, v1);
                if (r + 8 < M)
                    *(__half2*)&C[(size_t)(r + 8) * HD1 + c] = __floats2half2_rn(v2, v3);
                s0 = fmaf(v0, av_s[nt][0], fmaf(v1, av_s[nt][1], s0));
                s1 = fmaf(v2, av_s[nt][0], fmaf(v3, av_s[nt][1], s1));
                d0 = fmaf(v0, av_d[nt][0], fmaf(v1, av_d[nt][1], d0));
                d1 = fmaf(v2, av_d[nt][0], fmaf(v3, av_d[nt][1], d1));
            }
            s0 += __shfl_xor_sync(0xffffffffu, s0, 1); s0 += __shfl_xor_sync(0xffffffffu, s0, 2);
            s1 += __shfl_xor_sync(0xffffffffu, s1, 1); s1 += __shfl_xor_sync(0xffffffffu, s1, 2);
            d0 += __shfl_xor_sync(0xffffffffu, d0, 1); d0 += __shfl_xor_sync(0xffffffffu, d0, 2);
            d1 += __shfl_xor_sync(0xffffffffu, d1, 1); d1 += __shfl_xor_sync(0xffffffffu, d1, 2);
            if ((lane & 3) == 0) {
                if (r < M)     { atomicAdd(&als[r], s0);     atomicAdd(&ald[r], d0); }
                if (r + 8 < M) { atomicAdd(&als[r + 8], s1); atomicAdd(&ald[r + 8], d1); }
            }
        }
        __syncthreads();
    }
}

// ================= GEMM2: 4-stage pipelined =================
#define GM2_SMEM (4 * 2 * TILE_B)     // 81920 B

__global__ __launch_bounds__(256, 2) void k_mma2(
    const uint4* __restrict__ A1, const uint4* __restrict__ B1,
    __half* __restrict__ C, int M)
{
    constexpr int KT = 32;
    extern __shared__ char smem[];
    const uint32_t sbase = smem_u32(smem);
    const int tid = threadIdx.x, lane = tid & 31, wid = tid >> 5;
    const int wm = wid & 1, wn = wid >> 1;
    const int m0 = blockIdx.y * 128, n0 = blockIdx.x * 128;
    const int KW = KT * 4;

    float acc[4][4][4];
#pragma unroll
    for (int a = 0; a < 4; a++)
#pragma unroll
        for (int b = 0; b < 4; b++)
#pragma unroll
            for (int c = 0; c < 4; c++) acc[a][b][c] = 0.f;

    auto load_stage = [&](int ki, int s) {
        uint32_t sb = sbase + s * (2 * TILE_B);
#pragma unroll
        for (int i = 0; i < 2; i++) {
            int idx = tid + i * 256;
            int row = idx >> 2, ch = idx & 3;
            uint32_t soff = row * SMSTRIDE + ch * 16;
            int ar = min(m0 + row, M - 1);
            CP_ASYNC16(sb + soff,          A1 + (size_t)ar * KW + ki * 4 + ch);
            CP_ASYNC16(sb + TILE_B + soff, B1 + (size_t)(n0 + row) * KW + ki * 4 + ch);
        }
    };

    load_stage(0, 0); CP_COMMIT();
    load_stage(1, 1); CP_COMMIT();
    load_stage(2, 2); CP_COMMIT();

    for (int ki = 0; ki < KT; ki++) {
        if (ki + 3 < KT) load_stage(ki + 3, (ki + 3) & 3);
        CP_COMMIT();
        CP_WAIT3();
        __syncthreads();

        uint32_t sb  = sbase + (ki & 3) * (2 * TILE_B);
        uint32_t a1b = sb, b1b = sb + TILE_B;

#pragma unroll
        for (int k16 = 0; k16 < 2; k16++) {
            uint32_t bf1[8];
#pragma unroll
            for (int g = 0; g < 2; g++) {
                int nrow = wn * 32 + g * 16 + (lane & 7) + ((lane >> 4) << 3);
                int kb   = k16 * 32 + (((lane >> 3) & 1) << 4);
                LDSM_X4(&bf1[g * 4], b1b + nrow * SMSTRIDE + kb);
            }
#pragma unroll
            for (int mt = 0; mt < 4; mt++) {
                int arow = wm * 64 + mt * 16 + (lane & 7) + (((lane >> 3) & 1) << 3);
                int kb   = k16 * 32 + ((lane >> 4) << 4);
                uint32_t af[4];
                LDSM_X4(af, a1b + arow * SMSTRIDE + kb);
#pragma unroll
                for (int nt = 0; nt < 4; nt++) MMA_FP16(acc[mt][nt], af, &bf1[nt * 2]);
            }
        }
        __syncthreads();
    }

#pragma unroll
    for (int mt = 0; mt < 4; mt++) {
        int r = m0 + wm * 64 + mt * 16 + (lane >> 2);
#pragma unroll
        for (int nt = 0; nt < 4; nt++) {
            int c = n0 + wn * 32 + nt * 8 + (lane & 3) * 2;
            if (r < M)
                *(__half2*)&C[(size_t)r * D2 + c] = __floats2half2_rn(acc[mt][nt][0], acc[mt][nt][1]);
            if (r + 8 < M)
                *(__half2*)&C[(size_t)(r + 8) * D2 + c] = __floats2half2_rn(acc[mt][nt][2], acc[mt][nt][3]);
        }
    }
}

// ---------------- pool + FC (+ deg cleanup for next call) ----------------
__device__ __forceinline__ int lower_bound_batch(const int* b32, int is64, int key) {
    int lo = 0, hi = N_NODES;
    while (lo < hi) {
        int mid = (lo + hi) >> 1;
        int v = is64 ? b32[2 * mid] : b32[mid];
        if (v < key) lo = mid + 1; else hi = mid;
    }
    return lo;
}
__global__ __launch_bounds__(256) void k_pool_fc(
    const int* __restrict__ batch32, const int* __restrict__ ei32,
    const float* __restrict__ fcW, const float* __restrict__ fcb,
    float* __restrict__ out)
{
    int g = blockIdx.x, t = threadIdx.x;
    int gid = g * 256 + t;
    if (gid < N_NODES) g_deg[gid] = 0;

    __shared__ int s_lo, s_hi;
    __shared__ float pooled[D2];
    if (t == 0) {
        int is64 = detect_i64(ei32);
        s_lo = lower_bound_batch(batch32, is64, g);
        s_hi = lower_bound_batch(batch32, is64, g + 1);
    }
    __syncthreads();
    int lo = s_lo, hi = s_hi;
    float s = 0.f;
    for (int n = lo; n < hi; n++) s += g_out2[(size_t)n * D2 + t];
    float cnt = (float)(hi - lo);
    pooled[t] = s / fmaxf(cnt, 1.f);
    __syncthreads();
    if (t < OUT_DIM) {
        float acc = fcb[t];
        for (int d = 0; d < D2; d++) acc = fmaf(pooled[d], fcW[d * OUT_DIM + t], acc);
        out[g * OUT_DIM + t] = acc;
    }
}

// ---------------- launch ----------------
extern "C" void kernel_launch(void* const* d_in, const int* in_sizes, int n_in,
                              void* d_out, int out_size)
{
    const float* x      = (const float*)d_in[0];
    const int*   ei32   = (const int*)  d_in[1];
    const int*   bat32  = (const int*)  d_in[2];
    const float* W1     = (const float*)d_in[3];
    const float* a_src1 = (const float*)d_in[4];
    const float* a_dst1 = (const float*)d_in[5];
    const float* b1     = (const float*)d_in[6];
    const float* W2     = (const float*)d_in[7];
    const float* a_src2 = (const float*)d_in[8];
    const float* a_dst2 = (const float*)d_in[9];
    const float* b2     = (const float*)d_in[10];
    const float* fcW    = (const float*)d_in[11];
    const float* fcb    = (const float*)d_in[12];
    float* out = (float*)d_out;

    uint4 *xagg, *w1, *o1, *w2;
    __half *h2;
    float *als2, *ald2, *was2, *wad2;
    cudaGetSymbolAddress((void**)&xagg, g_xagg);
    cudaGetSymbolAddress((void**)&w1,   g_w1);
    cudaGetSymbolAddress((void**)&o1,   g_o1);
    cudaGetSymbolAddress((void**)&w2,   g_w2);
    cudaGetSymbolAddress((void**)&h2,   g_h2);
    cudaGetSymbolAddress((void**)&als2, g_als2);
    cudaGetSymbolAddress((void**)&ald2, g_ald2);
    cudaGetSymbolAddress((void**)&was2, g_was2);
    cudaGetSymbolAddress((void**)&wad2, g_wad2);

    cudaFuncSetAttribute((void*)k_mma1, cudaFuncAttributeMaxDynamicSharedMemorySize, GM1_SMEM);
    cudaFuncSetAttribute((void*)k_mma2, cudaFuncAttributeMaxDynamicSharedMemorySize, GM2_SMEM);

    const int MT = (N_NODES + 127) / 128;   // 391

    k_setup    <<<SETUP_GRID, 256>>>(W1, W2, a_src1, a_dst1, a_src2, a_dst2, ei32);  // 0
    k_scanlogit<<<SL_GRID, 1024>>>(x);                                               // 1
    k_scatter  <<<(E_TOT + 255) / 256, 256>>>();                                     // 2
    k_aggx     <<<(N_NODES * 32 + 255) / 256, 256>>>(x);                             // 3 (profiled)

    k_mma1<<<dim3(HD1 / 128, GB1_Y), 256, GM1_SMEM>>>(
        xagg, w1, (__half*)o1, N_NODES, b1, was2, wad2, als2, ald2);                 // 4

    k_mma2<<<dim3(D2 / 128, MT), 256, GM2_SMEM>>>(o1, w2, h2, N_NODES);              // 5

    k_agg2<<<(N_NODES * 32 + 255) / 256, 256>>>(b2);                                 // 6

    k_pool_fc<<<N_GRAPHS, 256>>>(bat32, ei32, fcW, fcb, out);                        // 7
}

// round 13
// speedup vs baseline: 1.0548x; 1.0548x over previous
#include <cuda_runtime.h>
#include <cuda_fp16.h>
#include <math.h>
#include <stdint.h>

// ---------------- problem constants ----------------
#define N_NODES 50000
#define N_EDGES 200000
#define E_TOT   (N_EDGES + N_NODES)   // 250000
#define F0      74
#define K1PAD   96
#define H1      4
#define D1      256
#define HD1     (H1 * D1)             // 1024
#define D2      256
#define N_GRAPHS 256
#define OUT_DIM 12
#define NEG_SLOPE 0.2f

// ---------------- scratch ----------------
__device__ __half g_h2 [(size_t)N_NODES * D2];
__device__ float  g_out2[(size_t)N_NODES * D2];
__device__ float g_als1[N_NODES * H1];
__device__ float g_ald1[N_NODES * H1];
__device__ float g_als2[N_NODES];
__device__ float g_ald2[N_NODES];
__device__ int   g_deg[N_NODES];      // zeroed by previous call's k_pool_fc (or static init)
__device__ int   g_rowptr[N_NODES + 1];
__device__ int   g_cursor[N_NODES];
__device__ int   g_esrc[E_TOT];       // CSR-ordered source node ids
__device__ float g_ew1[(size_t)E_TOT * H1];   // CSR-ordered layer-1 edge weights
__device__ int   g_src[E_TOT];
__device__ int   g_dst[E_TOT];

// attention projection vectors
__device__ float g_was1[K1PAD * H1];
__device__ float g_wad1[K1PAD * H1];
__device__ float g_was2[HD1];
__device__ float g_wad2[HD1];

// GEMM operands (fp16, K-major, 16B-aligned)
__device__ uint4 g_xagg[(size_t)N_NODES * H1 * K1PAD / 8];
__device__ uint4 g_w1  [(size_t)HD1 * K1PAD / 8];
__device__ uint4 g_o1  [(size_t)N_NODES * HD1 / 8];
__device__ uint4 g_w2  [(size_t)D2 * HD1 / 8];

// ---------------- PTX helpers ----------------
__device__ __forceinline__ uint32_t smem_u32(const void* p) {
    uint32_t a;
    asm("{ .reg .u64 t; cvta.to.shared.u64 t, %1; cvt.u32.u64 %0, t; }" : "=r"(a) : "l"(p));
    return a;
}
#define CP_ASYNC16(dst, src) \
    asm volatile("cp.async.cg.shared.global [%0], [%1], 16;" :: "r"(dst), "l"(src))
#define CP_COMMIT() asm volatile("cp.async.commit_group;" ::: "memory")
#define CP_WAIT1()  asm volatile("cp.async.wait_group 1;" ::: "memory")
#define CP_WAIT3()  asm volatile("cp.async.wait_group 3;" ::: "memory")

#define LDSM_X4(r, addr) \
    asm volatile("ldmatrix.sync.aligned.m8n8.x4.shared.b16 {%0,%1,%2,%3}, [%4];" \
        : "=r"((r)[0]), "=r"((r)[1]), "=r"((r)[2]), "=r"((r)[3]) : "r"(addr))

#define MMA_FP16(d, a, b) \
    asm volatile("mma.sync.aligned.m16n8k16.row.col.f32.f16.f16.f32 " \
        "{%0,%1,%2,%3}, {%4,%5,%6,%7}, {%8,%9}, {%0,%1,%2,%3};" \
        : "+f"((d)[0]), "+f"((d)[1]), "+f"((d)[2]), "+f"((d)[3]) \
        : "r"((a)[0]), "r"((a)[1]), "r"((a)[2]), "r"((a)[3]), "r"((b)[0]), "r"((b)[1]))

// ---------------- misc ----------------
__device__ __forceinline__ int detect_i64(const int* p) {
    return (p[1] | p[3] | p[5] | p[7]) == 0;
}
__device__ __forceinline__ float leaky(float v) { return v >= 0.f ? v : NEG_SLOPE * v; }

// ---------------- launch 0: setup ----------------
#define PW1_B 384
#define PW2_B 1024
#define AV1_B 37
#define AV2_B 128
#define PE_B  ((E_TOT + 255) / 256)   // 977
#define SETUP_GRID (PW1_B + PW2_B + AV1_B + AV2_B + PE_B)

__global__ __launch_bounds__(256) void k_setup(
    const float* __restrict__ W1, const float* __restrict__ W2,
    const float* __restrict__ as1, const float* __restrict__ ad1,
    const float* __restrict__ as2, const float* __restrict__ ad2,
    const int* __restrict__ ei32)
{
    int b = blockIdx.x, t = threadIdx.x, lane = t & 31;
    if (b < PW1_B) {
        int i = b * 256 + t;
        if (i < HD1 * K1PAD) {
            int n = i / K1PAD, k = i - n * K1PAD;
            float v = (k < F0) ? W1[(size_t)k * HD1 + n] : 0.f;
            ((__half*)g_w1)[i] = __float2half_rn(v);
        }
    } else if (b < PW1_B + PW2_B) {
        int i = (b - PW1_B) * 256 + t;
        if (i < D2 * HD1) {
            int n = i >> 10, k = i & 1023;
            ((__half*)g_w2)[i] = __float2half_rn(W2[(size_t)k * D2 + n]);
        }
    } else if (b < PW1_B + PW2_B + AV1_B) {
        int w = ((b - PW1_B - PW2_B) * 256 + t) >> 5;
        if (w < F0 * H1) {
            int k = w >> 2, h = w & 3;
            float s = 0.f, d = 0.f;
            for (int j = lane; j < D1; j += 32) {
                float wv = W1[(size_t)k * HD1 + h * D1 + j];
                s = fmaf(wv, as1[h * D1 + j], s);
                d = fmaf(wv, ad1[h * D1 + j], d);
            }
#pragma unroll
            for (int o = 16; o; o >>= 1) {
                s += __shfl_xor_sync(0xffffffffu, s, o);
                d += __shfl_xor_sync(0xffffffffu, d, o);
            }
            if (lane == 0) { g_was1[k * 4 + h] = s; g_wad1[k * 4 + h] = d; }
        }
    } else if (b < PW1_B + PW2_B + AV1_B + AV2_B) {
        int w = ((b - PW1_B - PW2_B - AV1_B) * 256 + t) >> 5;
        if (w < HD1) {
            float s = 0.f, d = 0.f;
            for (int j = lane; j < D2; j += 32) {
                float wv = W2[(size_t)w * D2 + j];
                s = fmaf(wv, as2[j], s);
                d = fmaf(wv, ad2[j], d);
            }
#pragma unroll
            for (int o = 16; o; o >>= 1) {
                s += __shfl_xor_sync(0xffffffffu, s, o);
                d += __shfl_xor_sync(0xffffffffu, d, o);
            }
            if (lane == 0) { g_was2[w] = s; g_wad2[w] = d; }
        }
    } else {
        int e = (b - PW1_B - PW2_B - AV1_B - AV2_B) * 256 + t;
        if (e >= E_TOT) return;
        int is64 = detect_i64(ei32);
        int s, d;
        if (e < N_EDGES) {
            s = is64 ? ei32[2 * (size_t)e]             : ei32[e];
            d = is64 ? ei32[2 * ((size_t)N_EDGES + e)] : ei32[N_EDGES + e];
        } else {
            s = d = e - N_EDGES;
        }
        g_src[e] = s;
        g_dst[e] = d;
        atomicAdd(&g_deg[d], 1);
    }
}

// ---------------- launch 1: scan (block 0) + layer-1 logits ----------------
#define SL_GRID (1 + (N_NODES + 31) / 32)

__global__ __launch_bounds__(1024) void k_scanlogit(const float* __restrict__ x) {
    if (blockIdx.x == 0) {
        __shared__ int sums[1024];
        int t = threadIdx.x;
        const int CH = (N_NODES + 1023) / 1024;
        int b = t * CH, e = min(b + CH, N_NODES);
        int s = 0;
        for (int i = b; i < e; i++) s += g_deg[i];
        sums[t] = s;
        __syncthreads();
        for (int off = 1; off < 1024; off <<= 1) {
            int v = (t >= off) ? sums[t - off] : 0;
            __syncthreads();
            sums[t] += v;
            __syncthreads();
        }
        int run = sums[t] - s;
        for (int i = b; i < e; i++) {
            g_rowptr[i] = run;
            g_cursor[i] = run;
            run += g_deg[i];
        }
        if (t == 1023) g_rowptr[N_NODES] = sums[1023];
        return;
    }
    int n = (blockIdx.x - 1) * 32 + (threadIdx.x >> 5);
    int lane = threadIdx.x & 31;
    if (n >= N_NODES) return;
    float4 s = make_float4(0, 0, 0, 0), d = make_float4(0, 0, 0, 0);
    for (int k = lane; k < F0; k += 32) {
        float xv = __ldg(&x[(size_t)n * F0 + k]);
        float4 a = *(const float4*)(g_was1 + k * 4);
        float4 bb = *(const float4*)(g_wad1 + k * 4);
        s.x = fmaf(xv, a.x, s.x);  s.y = fmaf(xv, a.y, s.y);
        s.z = fmaf(xv, a.z, s.z);  s.w = fmaf(xv, a.w, s.w);
        d.x = fmaf(xv, bb.x, d.x); d.y = fmaf(xv, bb.y, d.y);
        d.z = fmaf(xv, bb.z, d.z); d.w = fmaf(xv, bb.w, d.w);
    }
#pragma unroll
    for (int o = 16; o; o >>= 1) {
        s.x += __shfl_xor_sync(0xffffffffu, s.x, o);
        s.y += __shfl_xor_sync(0xffffffffu, s.y, o);
        s.z += __shfl_xor_sync(0xffffffffu, s.z, o);
        s.w += __shfl_xor_sync(0xffffffffu, s.w, o);
        d.x += __shfl_xor_sync(0xffffffffu, d.x, o);
        d.y += __shfl_xor_sync(0xffffffffu, d.y, o);
        d.z += __shfl_xor_sync(0xffffffffu, d.z, o);
        d.w += __shfl_xor_sync(0xffffffffu, d.w, o);
    }
    if (lane == 0) {
        *(float4*)(g_als1 + n * 4) = s;
        *(float4*)(g_ald1 + n * 4) = d;
    }
}

// ---------------- launch 2: scatter + layer-1 edge weights ----------------
__global__ void k_scatter() {
    int e = blockIdx.x * blockDim.x + threadIdx.x;
    if (e >= E_TOT) return;
    int s = g_src[e], d = g_dst[e];
    int p = atomicAdd(&g_cursor[d], 1);
    g_esrc[p] = s;
    const float4 as = *(const float4*)(g_als1 + s * 4);
    const float4 ad = *(const float4*)(g_ald1 + d * 4);
    float4 w;
    w.x = expf(leaky(as.x + ad.x));
    w.y = expf(leaky(as.y + ad.y));
    w.z = expf(leaky(as.z + ad.z));
    w.w = expf(leaky(as.w + ad.w));
    *(float4*)(g_ew1 + (size_t)p * 4) = w;
}

// ---------------- launch 3 (PROFILED): layer-1 aggregate ----------------
__global__ __launch_bounds__(256) void k_aggx(const float* __restrict__ x) {
    int n = (blockIdx.x * blockDim.x + threadIdx.x) >> 5;
    int lane = threadIdx.x & 31;
    if (n >= N_NODES) return;
    if (lane == 0) { g_als2[n] = 0.f; g_ald2[n] = 0.f; }
    int start = g_rowptr[n], deg = g_rowptr[n + 1] - start;

    float a[3][4];
#pragma unroll
    for (int g = 0; g < 3; g++)
#pragma unroll
        for (int h = 0; h < 4; h++) a[g][h] = 0.f;
    float4 den = make_float4(0, 0, 0, 0);

    for (int c0 = 0; c0 < deg; c0 += 32) {
        int j = c0 + lane;
        int srcj = 0;
        float4 e = make_float4(0, 0, 0, 0);
        if (j < deg) {
            srcj = g_esrc[start + j];
            e = *(const float4*)(g_ew1 + (size_t)(start + j) * 4);
            den.x += e.x; den.y += e.y; den.z += e.z; den.w += e.w;
        }
        int cnt = min(32, deg - c0);
        for (int jj = 0; jj < cnt; jj++) {
            int s  = __shfl_sync(0xffffffffu, srcj, jj);
            float e0 = __shfl_sync(0xffffffffu, e.x, jj);
            float e1 = __shfl_sync(0xffffffffu, e.y, jj);
            float e2 = __shfl_sync(0xffffffffu, e.z, jj);
            float e3 = __shfl_sync(0xffffffffu, e.w, jj);
            const float* xr = x + (size_t)s * F0;
            float x0 = __ldg(xr + lane);
            float x1 = __ldg(xr + lane + 32);
            float x2 = (lane + 64 < F0) ? __ldg(xr + lane + 64) : 0.f;
            a[0][0] = fmaf(x0, e0, a[0][0]); a[0][1] = fmaf(x0, e1, a[0][1]);
            a[0][2] = fmaf(x0, e2, a[0][2]); a[0][3] = fmaf(x0, e3, a[0][3]);
            a[1][0] = fmaf(x1, e0, a[1][0]); a[1][1] = fmaf(x1, e1, a[1][1]);
            a[1][2] = fmaf(x1, e2, a[1][2]); a[1][3] = fmaf(x1, e3, a[1][3]);
            a[2][0] = fmaf(x2, e0, a[2][0]); a[2][1] = fmaf(x2, e1, a[2][1]);
            a[2][2] = fmaf(x2, e2, a[2][2]); a[2][3] = fmaf(x2, e3, a[2][3]);
        }
    }
#pragma unroll
    for (int o = 16; o; o >>= 1) {
        den.x += __shfl_xor_sync(0xffffffffu, den.x, o);
        den.y += __shfl_xor_sync(0xffffffffu, den.y, o);
        den.z += __shfl_xor_sync(0xffffffffu, den.z, o);
        den.w += __shfl_xor_sync(0xffffffffu, den.w, o);
    }
    float inv[4];
    inv[0] = 1.f / (den.x + 1e-16f);
    inv[1] = 1.f / (den.y + 1e-16f);
    inv[2] = 1.f / (den.z + 1e-16f);
    inv[3] = 1.f / (den.w + 1e-16f);

    __half* xa = (__half*)g_xagg + (size_t)n * (H1 * K1PAD);
#pragma unroll
    for (int g = 0; g < 3; g++) {
        int col = lane + 32 * g;
#pragma unroll
        for (int h = 0; h < 4; h++)
            xa[h * K1PAD + col] = __float2half_rn(a[g][h] * inv[h]);
    }
}

// ---------------- layer-2 aggregate ----------------
__global__ __launch_bounds__(256) void k_agg2(const float* __restrict__ b2) {
    int n = (blockIdx.x * blockDim.x + threadIdx.x) >> 5;
    int lane = threadIdx.x & 31;
    if (n >= N_NODES) return;
    int start = g_rowptr[n], deg = g_rowptr[n + 1] - start;
    const float adn = g_ald2[n];

    float2 acc[4];
#pragma unroll
    for (int q = 0; q < 4; q++) acc[q] = make_float2(0.f, 0.f);
    float den = 0.f;

    for (int c0 = 0; c0 < deg; c0 += 32) {
        int j = c0 + lane;
        int srcj = 0;
        float e = 0.f;
        if (j < deg) {
            srcj = g_esrc[start + j];
            e = expf(leaky(g_als2[srcj] + adn));
            den += e;
        }
        int cnt = min(32, deg - c0);
        for (int jj = 0; jj < cnt; jj++) {
            int s   = __shfl_sync(0xffffffffu, srcj, jj);
            float ev = __shfl_sync(0xffffffffu, e, jj);
            const __half2* hr = (const __half2*)(g_h2 + (size_t)s * D2);
#pragma unroll
            for (int q = 0; q < 4; q++) {
                float2 v = __half22float2(__ldg(hr + lane + 32 * q));
                acc[q].x = fmaf(v.x, ev, acc[q].x);
                acc[q].y = fmaf(v.y, ev, acc[q].y);
            }
        }
    }
#pragma unroll
    for (int o = 16; o; o >>= 1) den += __shfl_xor_sync(0xffffffffu, den, o);
    float inv = 1.f / (den + 1e-16f);

#pragma unroll
    for (int q = 0; q < 4; q++) {
        int c = 2 * (lane + 32 * q);
        float2 o;
        o.x = fmaxf(fmaf(acc[q].x, inv, 0.f) + __ldg(b2 + c),     0.f);
        o.y = fmaxf(fmaf(acc[q].y, inv, 0.f) + __ldg(b2 + c + 1), 0.f);
        *(float2*)&g_out2[(size_t)n * D2 + c] = o;
    }
}

// ---------------- GEMM tiles ----------------
#define SMSTRIDE 80
#define TILE_B   (128 * SMSTRIDE)

// ================= GEMM1: persistent B-stationary =================
#define MT1 8
#define GB1_Y 49
#define GM1_SMEM (3 * TILE_B + 2 * 3 * TILE_B)    // 92160 B

__global__ __launch_bounds__(256, 2) void k_mma1(
    const uint4* __restrict__ A1, const uint4* __restrict__ B1,
    __half* __restrict__ C, int M,
    const float* __restrict__ bias,
    const float* __restrict__ avs, const float* __restrict__ avd,
    float* __restrict__ als, float* __restrict__ ald)
{
    extern __shared__ char smem[];
    const uint32_t sbase = smem_u32(smem);
    const uint32_t abase = sbase + 3 * TILE_B;
    const int tid = threadIdx.x, lane = tid & 31, wid = tid >> 5;
    const int wm = wid & 1, wn = wid >> 1;
    const int n0 = blockIdx.x * 128;
    const int head = n0 >> 8;
    const int tile0 = blockIdx.y * MT1;
    const int KW = 12;
    const int AST = H1 * KW;

    float bv[4][2], av_s[4][2], av_d[4][2];
#pragma unroll
    for (int nt = 0; nt < 4; nt++) {
        int c = n0 + wn * 32 + nt * 8 + (lane & 3) * 2;
        bv[nt][0]   = bias[c]; bv[nt][1]   = bias[c + 1];
        av_s[nt][0] = avs[c];  av_s[nt][1] = avs[c + 1];
        av_d[nt][0] = avd[c];  av_d[nt][1] = avd[c + 1];
    }

    auto load_A = [&](int tile, int s) {
        uint32_t sb = abase + s * (3 * TILE_B);
        int m0 = tile * 128;
#pragma unroll
        for (int i = 0; i < 6; i++) {
            int idx = tid + i * 256;
            int chunk = idx / 512, rem = idx & 511;
            int row = rem >> 2, ch = rem & 3;
            int ar = min(m0 + row, M - 1);
            CP_ASYNC16(sb + chunk * TILE_B + row * SMSTRIDE + ch * 16,
                       A1 + (size_t)ar * AST + head * KW + chunk * 4 + ch);
        }
    };

#pragma unroll
    for (int i = 0; i < 6; i++) {
        int idx = tid + i * 256;
        int chunk = idx / 512, rem = idx & 511;
        int row = rem >> 2, ch = rem & 3;
        CP_ASYNC16(sbase + chunk * TILE_B + row * SMSTRIDE + ch * 16,
                   B1 + (size_t)(n0 + row) * KW + chunk * 4 + ch);
    }
    load_A(tile0, 0);
    CP_COMMIT();

    for (int g = 0; g < MT1; g++) {
        if (g + 1 < MT1) load_A(tile0 + g + 1, (g + 1) & 1);
        CP_COMMIT();
        CP_WAIT1();
        __syncthreads();

        float acc[4][4][4];
#pragma unroll
        for (int a = 0; a < 4; a++)
#pragma unroll
            for (int b = 0; b < 4; b++)
#pragma unroll
                for (int c = 0; c < 4; c++) acc[a][b][c] = 0.f;

        uint32_t ab = abase + (g & 1) * (3 * TILE_B);
#pragma unroll
        for (int ki = 0; ki < 3; ki++) {
            uint32_t b1b = sbase + ki * TILE_B;
            uint32_t a1b = ab + ki * TILE_B;
#pragma unroll
            for (int k16 = 0; k16 < 2; k16++) {
                uint32_t bf1[8];
#pragma unroll
                for (int gg = 0; gg < 2; gg++) {
                    int nrow = wn * 32 + gg * 16 + (lane & 7) + ((lane >> 4) << 3);
                    int kb   = k16 * 32 + (((lane >> 3) & 1) << 4);
                    LDSM_X4(&bf1[gg * 4], b1b + nrow * SMSTRIDE + kb);
                }
#pragma unroll
                for (int mt = 0; mt < 4; mt++) {
                    int arow = wm * 64 + mt * 16 + (lane & 7) + (((lane >> 3) & 1) << 3);
                    int kb   = k16 * 32 + ((lane >> 4) << 4);
                    uint32_t af[4];
                    LDSM_X4(af, a1b + arow * SMSTRIDE + kb);
#pragma unroll
                    for (int nt = 0; nt < 4; nt++) MMA_FP16(acc[mt][nt], af, &bf1[nt * 2]);
                }
            }
        }

        int m0 = (tile0 + g) * 128;
#pragma unroll
        for (int mt = 0; mt < 4; mt++) {
            int r = m0 + wm * 64 + mt * 16 + (lane >> 2);
            float s0 = 0.f, s1 = 0.f, d0 = 0.f, d1 = 0.f;
#pragma unroll
            for (int nt = 0; nt < 4; nt++) {
                int c = n0 + wn * 32 + nt * 8 + (lane & 3) * 2;
                float v0 = fmaxf(acc[mt][nt][0] + bv[nt][0], 0.f);
                float v1 = fmaxf(acc[mt][nt][1] + bv[nt][1], 0.f);
                float v2 = fmaxf(acc[mt][nt][2] + bv[nt][0], 0.f);
                float v3 = fmaxf(acc[mt][nt][3] + bv[nt][1], 0.f);
                if (r < M)
                    *(__half2*)&C[(size_t)r * HD1 + c] = __floats2half2_rn(v0, v1);
                if (r + 8 < M)
                    *(__half2*)&C[(size_t)(r + 8) * HD1 + c] = __floats2half2_rn(v2, v3);
                s0 = fmaf(v0, av_s[nt][0], fmaf(v1, av_s[nt][1], s0));
                s1 = fmaf(v2, av_s[nt][0], fmaf(v3, av_s[nt][1], s1));
                d0 = fmaf(v0, av_d[nt][0], fmaf(v1, av_d[nt][1], d0));
                d1 = fmaf(v2, av_d[nt][0], fmaf(v3, av_d[nt][1], d1));
            }
            s0 += __shfl_xor_sync(0xffffffffu, s0, 1); s0 += __shfl_xor_sync(0xffffffffu, s0, 2);
            s1 += __shfl_xor_sync(0xffffffffu, s1, 1); s1 += __shfl_xor_sync(0xffffffffu, s1, 2);
            d0 += __shfl_xor_sync(0xffffffffu, d0, 1); d0 += __shfl_xor_sync(0xffffffffu, d0, 2);
            d1 += __shfl_xor_sync(0xffffffffu, d1, 1); d1 += __shfl_xor_sync(0xffffffffu, d1, 2);
            if ((lane & 3) == 0) {
                if (r < M)     { atomicAdd(&als[r], s0);     atomicAdd(&ald[r], d0); }
                if (r + 8 < M) { atomicAdd(&als[r + 8], s1); atomicAdd(&ald[r + 8], d1); }
            }
        }
        __syncthreads();
    }
}

// ================= GEMM2: 4-stage pipelined =================
#define GM2_SMEM (4 * 2 * TILE_B)     // 81920 B

__global__ __launch_bounds__(256, 2) void k_mma2(
    const uint4* __restrict__ A1, const uint4* __restrict__ B1,
    __half* __restrict__ C, int M)
{
    constexpr int KT = 32;
    extern __shared__ char smem[];
    const uint32_t sbase = smem_u32(smem);
    const int tid = threadIdx.x, lane = tid & 31, wid = tid >> 5;
    const int wm = wid & 1, wn = wid >> 1;
    const int m0 = blockIdx.y * 128, n0 = blockIdx.x * 128;
    const int KW = KT * 4;

    float acc[4][4][4];
#pragma unroll
    for (int a = 0; a < 4; a++)
#pragma unroll
        for (int b = 0; b < 4; b++)
#pragma unroll
            for (int c = 0; c < 4; c++) acc[a][b][c] = 0.f;

    auto load_stage = [&](int ki, int s) {
        uint32_t sb = sbase + s * (2 * TILE_B);
#pragma unroll
        for (int i = 0; i < 2; i++) {
            int idx = tid + i * 256;
            int row = idx >> 2, ch = idx & 3;
            uint32_t soff = row * SMSTRIDE + ch * 16;
            int ar = min(m0 + row, M - 1);
            CP_ASYNC16(sb + soff,          A1 + (size_t)ar * KW + ki * 4 + ch);
            CP_ASYNC16(sb + TILE_B + soff, B1 + (size_t)(n0 + row) * KW + ki * 4 + ch);
        }
    };

    load_stage(0, 0); CP_COMMIT();
    load_stage(1, 1); CP_COMMIT();
    load_stage(2, 2); CP_COMMIT();

    for (int ki = 0; ki < KT; ki++) {
        if (ki + 3 < KT) load_stage(ki + 3, (ki + 3) & 3);
        CP_COMMIT();
        CP_WAIT3();
        __syncthreads();

        uint32_t sb  = sbase + (ki & 3) * (2 * TILE_B);
        uint32_t a1b = sb, b1b = sb + TILE_B;

#pragma unroll
        for (int k16 = 0; k16 < 2; k16++) {
            uint32_t bf1[8];
#pragma unroll
            for (int g = 0; g < 2; g++) {
                int nrow = wn * 32 + g * 16 + (lane & 7) + ((lane >> 4) << 3);
                int kb   = k16 * 32 + (((lane >> 3) & 1) << 4);
                LDSM_X4(&bf1[g * 4], b1b + nrow * SMSTRIDE + kb);
            }
#pragma unroll
            for (int mt = 0; mt < 4; mt++) {
                int arow = wm * 64 + mt * 16 + (lane & 7) + (((lane >> 3) & 1) << 3);
                int kb   = k16 * 32 + ((lane >> 4) << 4);
                uint32_t af[4];
                LDSM_X4(af, a1b + arow * SMSTRIDE + kb);
#pragma unroll
                for (int nt = 0; nt < 4; nt++) MMA_FP16(acc[mt][nt], af, &bf1[nt * 2]);
            }
        }
        __syncthreads();
    }

#pragma unroll
    for (int mt = 0; mt < 4; mt++) {
        int r = m0 + wm * 64 + mt * 16 + (lane >> 2);
#pragma unroll
        for (int nt = 0; nt < 4; nt++) {
            int c = n0 + wn * 32 + nt * 8 + (lane & 3) * 2;
            if (r < M)
                *(__half2*)&C[(size_t)r * D2 + c] = __floats2half2_rn(acc[mt][nt][0], acc[mt][nt][1]);
            if (r + 8 < M)
                *(__half2*)&C[(size_t)(r + 8) * D2 + c] = __floats2half2_rn(acc[mt][nt][2], acc[mt][nt][3]);
        }
    }
}

// ---------------- pool + FC (+ deg cleanup for next call) ----------------
__device__ __forceinline__ int lower_bound_batch(const int* b32, int is64, int key) {
    int lo = 0, hi = N_NODES;
    while (lo < hi) {
        int mid = (lo + hi) >> 1;
        int v = is64 ? b32[2 * mid] : b32[mid];
        if (v < key) lo = mid + 1; else hi = mid;
    }
    return lo;
}
__global__ __launch_bounds__(256) void k_pool_fc(
    const int* __restrict__ batch32, const int* __restrict__ ei32,
    const float* __restrict__ fcW, const float* __restrict__ fcb,
    float* __restrict__ out)
{
    int g = blockIdx.x, t = threadIdx.x;
    int gid = g * 256 + t;
    if (gid < N_NODES) g_deg[gid] = 0;

    __shared__ int s_lo, s_hi;
    __shared__ float pooled[D2];
    if (t == 0) {
        int is64 = detect_i64(ei32);
        s_lo = lower_bound_batch(batch32, is64, g);
        s_hi = lower_bound_batch(batch32, is64, g + 1);
    }
    __syncthreads();
    int lo = s_lo, hi = s_hi;
    float s = 0.f;
    for (int n = lo; n < hi; n++) s += g_out2[(size_t)n * D2 + t];
    float cnt = (float)(hi - lo);
    pooled[t] = s / fmaxf(cnt, 1.f);
    __syncthreads();
    if (t < OUT_DIM) {
        float acc = fcb[t];
        for (int d = 0; d < D2; d++) acc = fmaf(pooled[d], fcW[d * OUT_DIM + t], acc);
        out[g * OUT_DIM + t] = acc;
    }
}

// ---------------- launch ----------------
extern "C" void kernel_launch(void* const* d_in, const int* in_sizes, int n_in,
                              void* d_out, int out_size)
{
    const float* x      = (const float*)d_in[0];
    const int*   ei32   = (const int*)  d_in[1];
    const int*   bat32  = (const int*)  d_in[2];
    const float* W1     = (const float*)d_in[3];
    const float* a_src1 = (const float*)d_in[4];
    const float* a_dst1 = (const float*)d_in[5];
    const float* b1     = (const float*)d_in[6];
    const float* W2     = (const float*)d_in[7];
    const float* a_src2 = (const float*)d_in[8];
    const float* a_dst2 = (const float*)d_in[9];
    const float* b2     = (const float*)d_in[10];
    const float* fcW    = (const float*)d_in[11];
    const float* fcb    = (const float*)d_in[12];
    float* out = (float*)d_out;

    uint4 *xagg, *w1, *o1, *w2;
    __half *h2;
    float *als2, *ald2, *was2, *wad2;
    cudaGetSymbolAddress((void**)&xagg, g_xagg);
    cudaGetSymbolAddress((void**)&w1,   g_w1);
    cudaGetSymbolAddress((void**)&o1,   g_o1);
    cudaGetSymbolAddress((void**)&w2,   g_w2);
    cudaGetSymbolAddress((void**)&h2,   g_h2);
    cudaGetSymbolAddress((void**)&als2, g_als2);
    cudaGetSymbolAddress((void**)&ald2, g_ald2);
    cudaGetSymbolAddress((void**)&was2, g_was2);
    cudaGetSymbolAddress((void**)&wad2, g_wad2);

    cudaFuncSetAttribute((void*)k_mma1, cudaFuncAttributeMaxDynamicSharedMemorySize, GM1_SMEM);
    cudaFuncSetAttribute((void*)k_mma2, cudaFuncAttributeMaxDynamicSharedMemorySize, GM2_SMEM);

    const int MT = (N_NODES + 127) / 128;   // 391

    k_setup    <<<SETUP_GRID, 256>>>(W1, W2, a_src1, a_dst1, a_src2, a_dst2, ei32);  // 0
    k_scanlogit<<<SL_GRID, 1024>>>(x);                                               // 1
    k_scatter  <<<(E_TOT + 255) / 256, 256>>>();                                     // 2
    k_aggx     <<<(N_NODES * 32 + 255) / 256, 256>>>(x);                             // 3 (profiled)

    k_mma1<<<dim3(HD1 / 128, GB1_Y), 256, GM1_SMEM>>>(
        xagg, w1, (__half*)o1, N_NODES, b1, was2, wad2, als2, ald2);                 // 4

    k_mma2<<<dim3(D2 / 128, MT), 256, GM2_SMEM>>>(o1, w2, h2, N_NODES);              // 5

    k_agg2<<<(N_NODES * 32 + 255) / 256, 256>>>(b2);                                 // 6

    k_pool_fc<<<N_GRAPHS, 256>>>(bat32, ei32, fcW, fcb, out);                        // 7
}